// round 7
// baseline (speedup 1.0000x reference)
#include <cuda_runtime.h>
#include <cstdint>
#include <math.h>

#define N_NODES 100000
#define N_EDGES 800000
#define DIM     256
#define N_MASK  10000
#define RPB     16
#define SCAN_BLK 512
#define N_SCAN_BLKS ((N_NODES + SCAN_BLK - 1) / SCAN_BLK)   // 196
#define NPB      512                                        // nodes per block in l1
#define L1_SMEM  (256 * 32 * 16)                            // 128KB: half of EW1

// ---------------- scratch (device globals) -----------------------------------
__device__ __align__(16) float  g_dinv[N_NODES];
__device__ __align__(16) float  g_EW1[DIM * DIM];
__device__ __align__(16) float  g_agg1[(size_t)N_NODES * DIM];
__device__ __align__(16) float  g_h2[(size_t)N_MASK * DIM];
__device__ int    g_cnt[N_NODES];
__device__ int    g_rowptr[N_NODES + 1];
__device__ int    g_blksum[256];
__device__ int    g_rank[N_EDGES];
__device__ __align__(8) float2 g_csr_p[N_EDGES];   // {w, bits: src | x[src]<<17}

// ---------------- CSR build ---------------------------------------------------
__global__ void k_hist(const int* __restrict__ dst) {
    int e = blockIdx.x * blockDim.x + threadIdx.x;
    if (e < N_EDGES) {
        int d = __ldg(dst + e);
        g_rank[e] = atomicAdd(&g_cnt[d], 1);
    }
}

__global__ void k_scan1() {
    __shared__ int s[SCAN_BLK];
    int t = threadIdx.x;
    int i = blockIdx.x * SCAN_BLK + t;
    int v = (i < N_NODES) ? g_cnt[i] : 0;
    if (i < N_NODES) g_dinv[i] = rsqrtf((float)v + 1.0f);   // +1 self-loop
    s[t] = v; __syncthreads();
#pragma unroll
    for (int off = 1; off < SCAN_BLK; off <<= 1) {
        int add = (t >= off) ? s[t - off] : 0;
        __syncthreads();
        s[t] += add;
        __syncthreads();
    }
    if (i < N_NODES) g_rowptr[i] = s[t] - v;
    if (t == SCAN_BLK - 1) g_blksum[blockIdx.x] = s[t];
}

__global__ void k_scan2_apply() {
    __shared__ int s[256];
    __shared__ int ex[256];
    int t = threadIdx.x;
    int v = (t < N_SCAN_BLKS) ? g_blksum[t] : 0;
    s[t] = v; __syncthreads();
#pragma unroll
    for (int off = 1; off < 256; off <<= 1) {
        int add = (t >= off) ? s[t - off] : 0;
        __syncthreads();
        s[t] += add;
        __syncthreads();
    }
    ex[t] = s[t] - v;
    __syncthreads();
    int i = blockIdx.x * 256 + t;
    if (i < N_NODES) g_rowptr[i] += ex[i >> 9];
    if (i == 0) g_rowptr[N_NODES] = N_EDGES;
}

// scatter, 8B packed payload, no atomics
__global__ void k_scatter(const int* __restrict__ src, const int* __restrict__ dst,
                          const int* __restrict__ x) {
    int e = blockIdx.x * blockDim.x + threadIdx.x;
    if (e >= N_EDGES) return;
    int s = __ldg(src + e), d = __ldg(dst + e);
    float w = g_dinv[s] * g_dinv[d];
    unsigned bits = (unsigned)s | ((unsigned)__ldg(x + s) << 17);
    int pos = g_rowptr[d] + g_rank[e];
    g_csr_p[pos] = make_float2(w, __uint_as_float(bits));
}

// ---------------- EW1 = emb @ W1, k-split x4 ----------------------------------
__global__ void k_ew1(const float* __restrict__ emb, const float* __restrict__ W1) {
    __shared__ float es[64];
    int row = blockIdx.x, j = threadIdx.x, kq = blockIdx.y * 64;
    if (j < 64) es[j] = __ldg(emb + row * DIM + kq + j);
    __syncthreads();
    float acc = 0.f;
#pragma unroll
    for (int k = 0; k < 64; k++) acc += es[k] * __ldg(W1 + (kq + k) * DIM + j);
    atomicAdd(&g_EW1[row * DIM + j], acc);
}

// ---------------- layer 1: SMEM-staged CSR gather ------------------------------
// grid (ceil(N/NPB), 2). Each block stages its 128KB half of EW1 into smem,
// then 16 warps each process 32 consecutive nodes, edge rows read from smem.
__global__ void __launch_bounds__(512) k_l1_stage(const int* __restrict__ x,
                                                  const float* __restrict__ b1) {
    extern __shared__ __align__(16) float4 sm[];   // [256 vocab][32 float4]
    int tid = threadIdx.x;
    int y = blockIdx.y;                            // feature half
    const float4* EW = reinterpret_cast<const float4*>(g_EW1);

    // stage: sm[v*32 + c] = EW1[v][y*128 + c*4 ..]
#pragma unroll
    for (int i = 0; i < 16; i++) {
        int idx = tid + i * 512;                   // 0..8191
        int v = idx >> 5, c = idx & 31;
        sm[idx] = EW[v * 64 + y * 32 + c];
    }
    __syncthreads();

    int warp = tid >> 5, lane = tid & 31;
    float4 bb = reinterpret_cast<const float4*>(b1)[y * 32 + lane];
    int nodebase = blockIdx.x * NPB + warp * 32;

    for (int i = 0; i < 32; i++) {
        int node = nodebase + i;
        if (node >= N_NODES) return;

        float dd = g_dinv[node];
        float ws = dd * dd;
        int xv = __ldg(x + node);
        float4 v = sm[xv * 32 + lane];
        float4 a0 = make_float4(bb.x + ws * v.x, bb.y + ws * v.y,
                                bb.z + ws * v.z, bb.w + ws * v.w);
        float4 a1 = make_float4(0.f, 0.f, 0.f, 0.f);

        int k = g_rowptr[node], end = g_rowptr[node + 1];
        for (; k + 1 < end; k += 2) {
            float2 p0 = __ldg(g_csr_p + k);
            float2 p1 = __ldg(g_csr_p + k + 1);
            int x0 = (int)(__float_as_uint(p0.y) >> 17);
            int x1 = (int)(__float_as_uint(p1.y) >> 17);
            float4 e0 = sm[x0 * 32 + lane];
            float4 e1 = sm[x1 * 32 + lane];
            a0.x += p0.x * e0.x; a0.y += p0.x * e0.y;
            a0.z += p0.x * e0.z; a0.w += p0.x * e0.w;
            a1.x += p1.x * e1.x; a1.y += p1.x * e1.y;
            a1.z += p1.x * e1.z; a1.w += p1.x * e1.w;
        }
        if (k < end) {
            float2 p = __ldg(g_csr_p + k);
            int xs = (int)(__float_as_uint(p.y) >> 17);
            float4 e = sm[xs * 32 + lane];
            a0.x += p.x * e.x; a0.y += p.x * e.y;
            a0.z += p.x * e.z; a0.w += p.x * e.w;
        }
        a0.x += a1.x; a0.y += a1.y; a0.z += a1.z; a0.w += a1.w;
        reinterpret_cast<float4*>(g_agg1)[(size_t)node * 64 + y * 32 + lane] = a0;
    }
}

// ---------------- layer 2: only masked nodes, warp-per-(row, half) ------------
__global__ void __launch_bounds__(256) k_l2_gather(const int* __restrict__ mask) {
    int warp = threadIdx.x >> 5, lane = threadIdx.x & 31;
    int i = blockIdx.x * 8 + warp;
    if (i >= N_MASK) return;
    int off = (blockIdx.y << 5) + lane;

    int node = __ldg(mask + i);
    const float4* A1 = reinterpret_cast<const float4*>(g_agg1);
    float dd = g_dinv[node];
    float ws = dd * dd;
    float4 v = A1[(size_t)node * 64 + off];
    float4 a0 = make_float4(ws * fmaxf(v.x, 0.f), ws * fmaxf(v.y, 0.f),
                            ws * fmaxf(v.z, 0.f), ws * fmaxf(v.w, 0.f));
    float4 a1 = make_float4(0.f, 0.f, 0.f, 0.f);

    int k = g_rowptr[node], end = g_rowptr[node + 1];
    for (; k + 1 < end; k += 2) {
        float2 p0 = __ldg(g_csr_p + k);
        float2 p1 = __ldg(g_csr_p + k + 1);
        int s0 = (int)(__float_as_uint(p0.y) & 0x1FFFFu);
        int s1 = (int)(__float_as_uint(p1.y) & 0x1FFFFu);
        float4 e0 = A1[(size_t)s0 * 64 + off];
        float4 e1 = A1[(size_t)s1 * 64 + off];
        a0.x += p0.x * fmaxf(e0.x, 0.f); a0.y += p0.x * fmaxf(e0.y, 0.f);
        a0.z += p0.x * fmaxf(e0.z, 0.f); a0.w += p0.x * fmaxf(e0.w, 0.f);
        a1.x += p1.x * fmaxf(e1.x, 0.f); a1.y += p1.x * fmaxf(e1.y, 0.f);
        a1.z += p1.x * fmaxf(e1.z, 0.f); a1.w += p1.x * fmaxf(e1.w, 0.f);
    }
    if (k < end) {
        float2 p = __ldg(g_csr_p + k);
        int s = (int)(__float_as_uint(p.y) & 0x1FFFFu);
        float4 e = A1[(size_t)s * 64 + off];
        a0.x += p.x * fmaxf(e.x, 0.f); a0.y += p.x * fmaxf(e.y, 0.f);
        a0.z += p.x * fmaxf(e.z, 0.f); a0.w += p.x * fmaxf(e.w, 0.f);
    }
    a0.x += a1.x; a0.y += a1.y; a0.z += a1.z; a0.w += a1.w;
    reinterpret_cast<float4*>(g_h2)[(size_t)i * 64 + off] = a0;
}

// ---------------- final: out = log_softmax(h2 @ W2 + b2) ----------------------
__global__ void __launch_bounds__(256) k_final(const float* __restrict__ W2,
                                               const float* __restrict__ b2,
                                               float* __restrict__ out) {
    __shared__ __align__(16) float As[RPB][DIM];
    int j = threadIdx.x;
    int base = blockIdx.x * RPB;

#pragma unroll
    for (int r = 0; r < RPB; r++)
        As[r][j] = g_h2[(size_t)(base + r) * DIM + j];
    __syncthreads();

    float acc[RPB];
    float bj = __ldg(b2 + j);
#pragma unroll
    for (int r = 0; r < RPB; r++) acc[r] = bj;

    for (int k4 = 0; k4 < DIM / 4; k4++) {
        float w0 = __ldg(W2 + (4 * k4 + 0) * DIM + j);
        float w1 = __ldg(W2 + (4 * k4 + 1) * DIM + j);
        float w2 = __ldg(W2 + (4 * k4 + 2) * DIM + j);
        float w3 = __ldg(W2 + (4 * k4 + 3) * DIM + j);
#pragma unroll
        for (int r = 0; r < RPB; r++) {
            float4 a = reinterpret_cast<const float4*>(&As[r][0])[k4];
            acc[r] += a.x * w0;
            acc[r] += a.y * w1;
            acc[r] += a.z * w2;
            acc[r] += a.w * w3;
        }
    }
    __syncthreads();

#pragma unroll
    for (int r = 0; r < RPB; r++) As[r][j] = acc[r];
    __syncthreads();

    int wid = j >> 5, lane = j & 31;
    for (int r = wid; r < RPB; r += 8) {
        float m = -INFINITY;
        for (int c = lane; c < DIM; c += 32) m = fmaxf(m, As[r][c]);
#pragma unroll
        for (int off = 16; off > 0; off >>= 1)
            m = fmaxf(m, __shfl_xor_sync(0xFFFFFFFFu, m, off));
        float sum = 0.f;
        for (int c = lane; c < DIM; c += 32) sum += expf(As[r][c] - m);
#pragma unroll
        for (int off = 16; off > 0; off >>= 1)
            sum += __shfl_xor_sync(0xFFFFFFFFu, sum, off);
        float lse = m + logf(sum);
        for (int c = lane; c < DIM; c += 32)
            out[(size_t)(base + r) * DIM + c] = As[r][c] - lse;
    }
}

// ---------------- launch -------------------------------------------------------
extern "C" void kernel_launch(void* const* d_in, const int* in_sizes, int n_in,
                              void* d_out, int out_size) {
    const int*   x    = (const int*)  d_in[0];
    const int*   ei   = (const int*)  d_in[1];
    const int*   mask = (const int*)  d_in[2];
    const float* emb  = (const float*)d_in[3];
    const float* W1   = (const float*)d_in[4];
    const float* b1   = (const float*)d_in[5];
    const float* W2   = (const float*)d_in[6];
    const float* b2   = (const float*)d_in[7];
    float* out = (float*)d_out;

    const int* src = ei;
    const int* dst = ei + N_EDGES;

    void *p_cnt = nullptr, *p_ew1 = nullptr;
    cudaGetSymbolAddress(&p_cnt, g_cnt);
    cudaGetSymbolAddress(&p_ew1, g_EW1);
    cudaMemsetAsync(p_cnt, 0, N_NODES * sizeof(int));
    cudaMemsetAsync(p_ew1, 0, DIM * DIM * sizeof(float));

    // opt into 128KB dynamic smem for the staged gather (idempotent, capture-safe)
    cudaFuncSetAttribute(k_l1_stage, cudaFuncAttributeMaxDynamicSharedMemorySize,
                         L1_SMEM);

    // CSR build
    k_hist<<<(N_EDGES + 255) / 256, 256>>>(dst);
    k_scan1<<<N_SCAN_BLKS, SCAN_BLK>>>();
    k_scan2_apply<<<(N_NODES + 255) / 256, 256>>>();
    k_scatter<<<(N_EDGES + 255) / 256, 256>>>(src, dst, x);

    // EW1 = emb @ W1 (k-split x4)
    {
        dim3 g(DIM, 4);
        k_ew1<<<g, DIM>>>(emb, W1);
    }

    // layer 1: SMEM-staged full-node CSR gather (self-loop + b1 fused)
    {
        dim3 g((N_NODES + NPB - 1) / NPB, 2);
        k_l1_stage<<<g, 512, L1_SMEM>>>(x, b1);
    }

    // layer 2: only masked nodes (relu fused), feature-split x2
    {
        dim3 g((N_MASK + 7) / 8, 2);
        k_l2_gather<<<g, 256>>>(mask);
    }

    // masked GEMM + bias + log_softmax
    k_final<<<N_MASK / RPB, 256>>>(W2, b2, out);
}